// round 1
// baseline (speedup 1.0000x reference)
#include <cuda_runtime.h>
#include <math.h>

#define Bn 16
#define Cn 128
#define Ln 2048
#define RSQRTC 0.08838834764831845f   // 1/sqrt(128)
#define NKCH 8
#define KCH (Ln / NKCH)               // 256

// scratch for split-K softmax (device globals: no allocation allowed)
__device__ float g_pm[Bn * Ln * NKCH];
__device__ float g_ps[Bn * Ln * NKCH];
__device__ float g_M[Bn * Ln];
__device__ float g_Sinv[Bn * Ln];

// packed fp32x2 FMA (sm_100+): 2x throughput vs scalar 3-reg FFMA on B300
#define FMA2(d, a, b) asm("fma.rn.f32x2 %0, %1, %2, %0;" : "+l"(d) : "l"(a), "l"(b))

__device__ __forceinline__ unsigned long long pack2(float x) {
    unsigned long long d;
    unsigned int u = __float_as_uint(x);
    asm("mov.b64 %0, {%1, %1};" : "=l"(d) : "r"(u));
    return d;
}
__device__ __forceinline__ float2 unpack2(unsigned long long v) {
    unsigned int lo, hi;
    asm("mov.b64 {%0, %1}, %2;" : "=r"(lo), "=r"(hi) : "l"(v));
    return make_float2(__uint_as_float(lo), __uint_as_float(hi));
}

// ---------------------------------------------------------------------------
// K1: S^T[b,k,q] = (sum_c K[b,c,k] * Q[b,c,q]) * rsqrt(C) + log(mask[b,k]+1e-6)
// Written directly into the transposed attention output region.
// Tile: 128(k) x 128(q), BK=16 over c. 256 threads, 8x8 microtile.
// ---------------------------------------------------------------------------
__global__ __launch_bounds__(256) void k_energy(
    const float* __restrict__ Q, const float* __restrict__ Kp,
    const float* __restrict__ mask, float* __restrict__ attn)
{
    __shared__ float As[16][128];  // K slice: [c][k]
    __shared__ float Bs[16][128];  // Q slice: [c][q]

    int b  = blockIdx.z;
    int k0 = blockIdx.y * 128;
    int q0 = blockIdx.x * 128;
    const float* Kb = Kp + (size_t)b * Cn * Ln;
    const float* Qb = Q  + (size_t)b * Cn * Ln;

    int t  = threadIdx.x;
    int tx = t & 15;   // q microtile
    int ty = t >> 4;   // k microtile

    unsigned long long acc[8][4];
#pragma unroll
    for (int i = 0; i < 8; i++)
#pragma unroll
        for (int j = 0; j < 4; j++) acc[i][j] = 0ULL;

    for (int c0 = 0; c0 < Cn; c0 += 16) {
#pragma unroll
        for (int r = 0; r < 2; r++) {
            int s  = t + r * 256;
            int cc = s >> 5, c4 = s & 31;
            *(float4*)&As[cc][c4 * 4] =
                *(const float4*)(Kb + (size_t)(c0 + cc) * Ln + k0 + c4 * 4);
            *(float4*)&Bs[cc][c4 * 4] =
                *(const float4*)(Qb + (size_t)(c0 + cc) * Ln + q0 + c4 * 4);
        }
        __syncthreads();
#pragma unroll
        for (int kk = 0; kk < 16; kk++) {
            float a[8];
            *(float4*)&a[0] = *(float4*)&As[kk][ty * 8];
            *(float4*)&a[4] = *(float4*)&As[kk][ty * 8 + 4];
            unsigned long long bp[4];
            const unsigned long long* brow =
                (const unsigned long long*)&Bs[kk][tx * 8];
#pragma unroll
            for (int j = 0; j < 4; j++) bp[j] = brow[j];
#pragma unroll
            for (int i = 0; i < 8; i++) {
                unsigned long long ap = pack2(a[i]);
#pragma unroll
                for (int j = 0; j < 4; j++) FMA2(acc[i][j], ap, bp[j]);
            }
        }
        __syncthreads();
    }

    float* Ab = attn + (size_t)b * Ln * Ln;
#pragma unroll
    for (int i = 0; i < 8; i++) {
        int kg = k0 + ty * 8 + i;
        float lm = logf(mask[b * Ln + kg] + 1e-6f);
        float2 p0 = unpack2(acc[i][0]);
        float2 p1 = unpack2(acc[i][1]);
        float2 p2 = unpack2(acc[i][2]);
        float2 p3 = unpack2(acc[i][3]);
        float4 o0 = make_float4(fmaf(p0.x, RSQRTC, lm), fmaf(p0.y, RSQRTC, lm),
                                fmaf(p1.x, RSQRTC, lm), fmaf(p1.y, RSQRTC, lm));
        float4 o1 = make_float4(fmaf(p2.x, RSQRTC, lm), fmaf(p2.y, RSQRTC, lm),
                                fmaf(p3.x, RSQRTC, lm), fmaf(p3.y, RSQRTC, lm));
        float* dst = Ab + (size_t)kg * Ln + q0 + tx * 8;
        *(float4*)dst       = o0;
        *(float4*)(dst + 4) = o1;
    }
}

// ---------------------------------------------------------------------------
// K2a: split-K online (max, expsum) partials per (b,q) over 8 k-chunks
// ---------------------------------------------------------------------------
__global__ __launch_bounds__(256) void k_smax_part(const float* __restrict__ attn)
{
    int b  = blockIdx.z;
    int kc = blockIdx.y;
    int q  = blockIdx.x * 256 + threadIdx.x;
    const float* base = attn + (size_t)b * Ln * Ln + q;

    float m = -1e30f, s = 0.f;
    int kbeg = kc * KCH;
#pragma unroll 4
    for (int k = kbeg; k < kbeg + KCH; k++) {
        float v  = __ldg(base + (size_t)k * Ln);
        float nm = fmaxf(m, v);
        s = s * __expf(m - nm) + __expf(v - nm);
        m = nm;
    }
    int idx = (b * Ln + q) * NKCH + kc;
    g_pm[idx] = m;
    g_ps[idx] = s;
}

// K2b: combine partials -> row max M and 1/sum
__global__ __launch_bounds__(256) void k_smax_comb()
{
    int i = blockIdx.x * 256 + threadIdx.x;  // 0 .. B*L-1
    float pm[NKCH], ps[NKCH];
    float M = -1e30f;
#pragma unroll
    for (int c = 0; c < NKCH; c++) {
        pm[c] = g_pm[i * NKCH + c];
        ps[c] = g_ps[i * NKCH + c];
        M = fmaxf(M, pm[c]);
    }
    float S = 0.f;
#pragma unroll
    for (int c = 0; c < NKCH; c++) S += ps[c] * __expf(pm[c] - M);
    g_M[i]    = M;
    g_Sinv[i] = 1.f / S;
}

// K2c: write normalized masked attention in place
__global__ __launch_bounds__(256) void k_smax_write(
    float* __restrict__ attn, const float* __restrict__ mask)
{
    int b  = blockIdx.z;
    int kc = blockIdx.y;
    int q  = blockIdx.x * 256 + threadIdx.x;
    float* base = attn + (size_t)b * Ln * Ln + q;
    int bq = b * Ln + q;
    float M  = g_M[bq];
    float Si = g_Sinv[bq];
    int kbeg = kc * KCH;
#pragma unroll 8
    for (int k = kbeg; k < kbeg + KCH; k++) {
        float v = base[(size_t)k * Ln];
        float w = __expf(v - M) * Si * mask[b * Ln + k];
        base[(size_t)k * Ln] = w;
    }
}

// ---------------------------------------------------------------------------
// K3: out[b,c,q] = sum_k V[b,c,k] * attn^T[b,k,q]
// Tile: 128(c) x 128(q), BK=16 over k. V transposed into smem on load.
// ---------------------------------------------------------------------------
__global__ __launch_bounds__(256) void k_out(
    const float* __restrict__ V, const float* __restrict__ attn,
    float* __restrict__ out)
{
    __shared__ float As[16][132];  // V^T slice: [k][c] (+4 pad)
    __shared__ float Bs[16][128];  // attn slice: [k][q]

    int b  = blockIdx.z;
    int q0 = blockIdx.x * 128;
    const float* Vb = V    + (size_t)b * Cn * Ln;
    const float* Ab = attn + (size_t)b * Ln * Ln;

    int t  = threadIdx.x;
    int tx = t & 15;   // q microtile
    int ty = t >> 4;   // c microtile

    unsigned long long acc[8][4];
#pragma unroll
    for (int i = 0; i < 8; i++)
#pragma unroll
        for (int j = 0; j < 4; j++) acc[i][j] = 0ULL;

    for (int k0 = 0; k0 < Ln; k0 += 16) {
#pragma unroll
        for (int r = 0; r < 2; r++) {
            int s = t + r * 256;
            // V: read rows (c, 16 contiguous k), store transposed
            int c = s >> 2, k4 = s & 3;
            float4 v = *(const float4*)(Vb + (size_t)c * Ln + k0 + k4 * 4);
            As[k4 * 4 + 0][c] = v.x;
            As[k4 * 4 + 1][c] = v.y;
            As[k4 * 4 + 2][c] = v.z;
            As[k4 * 4 + 3][c] = v.w;
            // attn rows: contiguous
            int cc = s >> 5, c4 = s & 31;
            *(float4*)&Bs[cc][c4 * 4] =
                *(const float4*)(Ab + (size_t)(k0 + cc) * Ln + q0 + c4 * 4);
        }
        __syncthreads();
#pragma unroll
        for (int kk = 0; kk < 16; kk++) {
            float a[8];
            *(float4*)&a[0] = *(float4*)&As[kk][ty * 8];
            *(float4*)&a[4] = *(float4*)&As[kk][ty * 8 + 4];
            unsigned long long bp[4];
            const unsigned long long* brow =
                (const unsigned long long*)&Bs[kk][tx * 8];
#pragma unroll
            for (int j = 0; j < 4; j++) bp[j] = brow[j];
#pragma unroll
            for (int i = 0; i < 8; i++) {
                unsigned long long ap = pack2(a[i]);
#pragma unroll
                for (int j = 0; j < 4; j++) FMA2(acc[i][j], ap, bp[j]);
            }
        }
        __syncthreads();
    }

#pragma unroll
    for (int i = 0; i < 8; i++) {
        int cg = ty * 8 + i;
        float2 p0 = unpack2(acc[i][0]);
        float2 p1 = unpack2(acc[i][1]);
        float2 p2 = unpack2(acc[i][2]);
        float2 p3 = unpack2(acc[i][3]);
        float4 o0 = make_float4(p0.x, p0.y, p1.x, p1.y);
        float4 o1 = make_float4(p2.x, p2.y, p3.x, p3.y);
        float* dst = out + (size_t)b * Cn * Ln + (size_t)cg * Ln + q0 + tx * 8;
        *(float4*)dst       = o0;
        *(float4*)(dst + 4) = o1;
    }
}

// ---------------------------------------------------------------------------
extern "C" void kernel_launch(void* const* d_in, const int* in_sizes, int n_in,
                              void* d_out, int out_size)
{
    const float* Q    = (const float*)d_in[0];
    const float* K    = (const float*)d_in[1];
    const float* V    = (const float*)d_in[2];
    const float* mask = (const float*)d_in[3];

    float* out  = (float*)d_out;                      // [B, C, L]
    float* attn = out + (size_t)Bn * Cn * Ln;         // [B, Lk, Lq] (transposed)

    dim3 g1(Ln / 128, Ln / 128, Bn);
    k_energy<<<g1, 256>>>(Q, K, mask, attn);

    dim3 gs(Ln / 256, NKCH, Bn);
    k_smax_part<<<gs, 256>>>(attn);
    k_smax_comb<<<(Bn * Ln) / 256, 256>>>();
    k_smax_write<<<gs, 256>>>(attn, mask);

    dim3 g3(Ln / 128, 1, Bn);
    k_out<<<g3, 256>>>(V, attn, out);
}

// round 4
// speedup vs baseline: 1.0868x; 1.0868x over previous
#include <cuda_runtime.h>
#include <math.h>

#define Bn 16
#define Cn 128
#define Ln 2048
#define RSQRTC 0.08838834764831845f   // 1/sqrt(128)
#define NKB 16                        // k-blocks of 128 (= split-K partials)

// scratch (device globals: no allocation allowed)
__device__ float g_ps[Bn * Ln * NKB];
__device__ float g_Sinv[Bn * Ln];

// packed fp32x2 FMA (sm_100+): 2x throughput vs scalar 3-reg FFMA on B300
#define FMA2(d, a, b) asm("fma.rn.f32x2 %0, %1, %2, %0;" : "+l"(d) : "l"(a), "l"(b))

__device__ __forceinline__ unsigned long long pack2(float x) {
    unsigned long long d;
    unsigned int u = __float_as_uint(x);
    asm("mov.b64 %0, {%1, %1};" : "=l"(d) : "r"(u));
    return d;
}
__device__ __forceinline__ float2 unpack2(unsigned long long v) {
    unsigned int lo, hi;
    asm("mov.b64 {%0, %1}, %2;" : "=r"(lo), "=r"(hi) : "l"(v));
    return make_float2(__uint_as_float(lo), __uint_as_float(hi));
}

// ---------------------------------------------------------------------------
// K1: P[b,k,q] = exp( (sum_c K[b,c,k]*Q[b,c,q]) * rsqrt(C) + log(mask[b,k]+1e-6) )
// written into the transposed attention output region, PLUS per-(b,q) partial
// sums of P over this block's 128 k's -> g_ps[(b,q)*NKB + kblock].
// No max-subtraction: scores are bounded (~[-20, +7]) so exp is fp32-safe.
// Tile: 128(k) x 128(q), BK=16 over c. 256 threads, 8x8 microtile.
// ---------------------------------------------------------------------------
__global__ __launch_bounds__(256) void k_energy(
    const float* __restrict__ Q, const float* __restrict__ Kp,
    const float* __restrict__ mask, float* __restrict__ attn)
{
    __shared__ float As[16][128];  // K slice: [c][k]
    __shared__ float Bs[16][128];  // Q slice: [c][q]

    int b  = blockIdx.z;
    int k0 = blockIdx.y * 128;
    int q0 = blockIdx.x * 128;
    const float* Kb = Kp + (size_t)b * Cn * Ln;
    const float* Qb = Q  + (size_t)b * Cn * Ln;

    int t  = threadIdx.x;
    int tx = t & 15;   // q microtile
    int ty = t >> 4;   // k microtile

    unsigned long long acc[8][4];
#pragma unroll
    for (int i = 0; i < 8; i++)
#pragma unroll
        for (int j = 0; j < 4; j++) acc[i][j] = 0ULL;

    for (int c0 = 0; c0 < Cn; c0 += 16) {
#pragma unroll
        for (int r = 0; r < 2; r++) {
            int s  = t + r * 256;
            int cc = s >> 5, c4 = s & 31;
            *(float4*)&As[cc][c4 * 4] =
                *(const float4*)(Kb + (size_t)(c0 + cc) * Ln + k0 + c4 * 4);
            *(float4*)&Bs[cc][c4 * 4] =
                *(const float4*)(Qb + (size_t)(c0 + cc) * Ln + q0 + c4 * 4);
        }
        __syncthreads();
#pragma unroll
        for (int kk = 0; kk < 16; kk++) {
            float a[8];
            *(float4*)&a[0] = *(float4*)&As[kk][ty * 8];
            *(float4*)&a[4] = *(float4*)&As[kk][ty * 8 + 4];
            unsigned long long bp[4];
            const unsigned long long* brow =
                (const unsigned long long*)&Bs[kk][tx * 8];
#pragma unroll
            for (int j = 0; j < 4; j++) bp[j] = brow[j];
#pragma unroll
            for (int i = 0; i < 8; i++) {
                unsigned long long ap = pack2(a[i]);
#pragma unroll
                for (int j = 0; j < 4; j++) FMA2(acc[i][j], ap, bp[j]);
            }
        }
        __syncthreads();
    }

    // epilogue: exp + store + per-column partial sums
    float* Ab = attn + (size_t)b * Ln * Ln;
    float qsum[8];
#pragma unroll
    for (int j = 0; j < 8; j++) qsum[j] = 0.f;

#pragma unroll
    for (int i = 0; i < 8; i++) {
        int kg = k0 + ty * 8 + i;
        float lm = __logf(mask[b * Ln + kg] + 1e-6f);
        float v[8];
        float2 p;
        p = unpack2(acc[i][0]); v[0] = p.x; v[1] = p.y;
        p = unpack2(acc[i][1]); v[2] = p.x; v[3] = p.y;
        p = unpack2(acc[i][2]); v[4] = p.x; v[5] = p.y;
        p = unpack2(acc[i][3]); v[6] = p.x; v[7] = p.y;
        float e[8];
#pragma unroll
        for (int j = 0; j < 8; j++) {
            e[j] = __expf(fmaf(v[j], RSQRTC, lm));
            qsum[j] += e[j];
        }
        float* dst = Ab + (size_t)kg * Ln + q0 + tx * 8;
        *(float4*)dst       = make_float4(e[0], e[1], e[2], e[3]);
        *(float4*)(dst + 4) = make_float4(e[4], e[5], e[6], e[7]);
    }

    // reduce qsum over ty (16-way) via smem (reuse As)
    float (*red)[128] = As;
    __syncthreads();
#pragma unroll
    for (int j = 0; j < 8; j++) red[ty][tx * 8 + j] = qsum[j];
    __syncthreads();
    if (t < 128) {
        float s = 0.f;
#pragma unroll
        for (int r = 0; r < 16; r++) s += red[r][t];
        g_ps[((size_t)b * Ln + q0 + t) * NKB + blockIdx.y] = s;
    }
}

// ---------------------------------------------------------------------------
// K2: combine split-K partial sums -> 1/S per (b,q)
// ---------------------------------------------------------------------------
__global__ __launch_bounds__(256) void k_sinv()
{
    int i = blockIdx.x * 256 + threadIdx.x;  // 0 .. B*L-1
    float S = 0.f;
#pragma unroll
    for (int c = 0; c < NKB; c++) S += g_ps[(size_t)i * NKB + c];
    g_Sinv[i] = 1.f / S;
}

// ---------------------------------------------------------------------------
// K3: normalize attention in-place while computing
//     out[b,c,q] = sum_k V[b,c,k] * w[b,k,q],  w = P * Sinv[q] * mask[k]
// Tile: 128(c) x 128(q), BK=16 over k. V transposed into smem on load.
// ---------------------------------------------------------------------------
__global__ __launch_bounds__(256) void k_out(
    const float* __restrict__ V, float* __restrict__ attn,
    const float* __restrict__ mask, float* __restrict__ out)
{
    __shared__ float As[16][132];  // V^T slice: [k][c] (+4 pad)
    __shared__ float Bs[16][128];  // w slice: [k][q]

    int b  = blockIdx.z;
    int q0 = blockIdx.x * 128;
    const float* Vb = V    + (size_t)b * Cn * Ln;
    float*       Ab = attn + (size_t)b * Ln * Ln;

    int t  = threadIdx.x;
    int tx = t & 15;   // q microtile
    int ty = t >> 4;   // c microtile

    // per-thread cached Sinv for the 4 q's this thread loads in the fill loop
    float4 si0 = *(const float4*)&g_Sinv[(size_t)b * Ln + q0 + (t & 31) * 4];

    unsigned long long acc[8][4];
#pragma unroll
    for (int i = 0; i < 8; i++)
#pragma unroll
        for (int j = 0; j < 4; j++) acc[i][j] = 0ULL;

    for (int k0 = 0; k0 < Ln; k0 += 16) {
#pragma unroll
        for (int r = 0; r < 2; r++) {
            int s = t + r * 256;
            // V: read rows (c, 16 contiguous k), store transposed
            int c = s >> 2, k4 = s & 3;
            float4 v = *(const float4*)(Vb + (size_t)c * Ln + k0 + k4 * 4);
            As[k4 * 4 + 0][c] = v.x;
            As[k4 * 4 + 1][c] = v.y;
            As[k4 * 4 + 2][c] = v.z;
            As[k4 * 4 + 3][c] = v.w;
            // attn rows: load P, scale to normalized w, write back + to smem
            int cc = s >> 5, c4 = s & 31;
            int kg = k0 + cc;
            float* src = Ab + (size_t)kg * Ln + q0 + c4 * 4;
            float4 p = *(float4*)src;
            float mk = __ldg(mask + b * Ln + kg);
            p.x *= si0.x * mk;
            p.y *= si0.y * mk;
            p.z *= si0.z * mk;
            p.w *= si0.w * mk;
            *(float4*)src = p;                 // final attention output
            *(float4*)&Bs[cc][c4 * 4] = p;
        }
        __syncthreads();
#pragma unroll
        for (int kk = 0; kk < 16; kk++) {
            float a[8];
            *(float4*)&a[0] = *(float4*)&As[kk][ty * 8];
            *(float4*)&a[4] = *(float4*)&As[kk][ty * 8 + 4];
            unsigned long long bp[4];
            const unsigned long long* brow =
                (const unsigned long long*)&Bs[kk][tx * 8];
#pragma unroll
            for (int j = 0; j < 4; j++) bp[j] = brow[j];
#pragma unroll
            for (int i = 0; i < 8; i++) {
                unsigned long long ap = pack2(a[i]);
#pragma unroll
                for (int j = 0; j < 4; j++) FMA2(acc[i][j], ap, bp[j]);
            }
        }
        __syncthreads();
    }

#pragma unroll
    for (int i = 0; i < 8; i++) {
        int cg = ty * 8 + i;
        float2 p0 = unpack2(acc[i][0]);
        float2 p1 = unpack2(acc[i][1]);
        float2 p2 = unpack2(acc[i][2]);
        float2 p3 = unpack2(acc[i][3]);
        float4 o0 = make_float4(p0.x, p0.y, p1.x, p1.y);
        float4 o1 = make_float4(p2.x, p2.y, p3.x, p3.y);
        float* dst = out + (size_t)b * Cn * Ln + (size_t)cg * Ln + q0 + tx * 8;
        *(float4*)dst       = o0;
        *(float4*)(dst + 4) = o1;
    }
}

// ---------------------------------------------------------------------------
extern "C" void kernel_launch(void* const* d_in, const int* in_sizes, int n_in,
                              void* d_out, int out_size)
{
    const float* Q    = (const float*)d_in[0];
    const float* K    = (const float*)d_in[1];
    const float* V    = (const float*)d_in[2];
    const float* mask = (const float*)d_in[3];

    float* out  = (float*)d_out;                      // [B, C, L]
    float* attn = out + (size_t)Bn * Cn * Ln;         // [B, Lk, Lq] (transposed)

    dim3 g1(Ln / 128, Ln / 128, Bn);
    k_energy<<<g1, 256>>>(Q, K, mask, attn);

    k_sinv<<<(Bn * Ln) / 256, 256>>>();

    dim3 g3(Ln / 128, 1, Bn);
    k_out<<<g3, 256>>>(V, attn, mask, out);
}

// round 6
// speedup vs baseline: 1.7956x; 1.6522x over previous
#include <cuda_runtime.h>
#include <cuda_bf16.h>
#include <math.h>
#include <cstdint>

#define Bn 16
#define Cn 128
#define Ln 2048
#define RSQRTC 0.08838834764831845f   // 1/sqrt(128)
#define NKB 16                        // k-blocks of 128 (split-K partials)

// ---------------- device-global scratch (no allocation allowed) ----------------
__device__ float g_ps[Bn * Ln * NKB];
__device__ float g_Sinv[Bn * Ln];
__device__ __nv_bfloat16 g_Qt_h[Bn * Ln * Cn];  // [b][q][c] hi
__device__ __nv_bfloat16 g_Qt_l[Bn * Ln * Cn];  // lo
__device__ __nv_bfloat16 g_Kt_h[Bn * Ln * Cn];  // [b][k][c]
__device__ __nv_bfloat16 g_Kt_l[Bn * Ln * Cn];
__device__ __nv_bfloat16 g_V_h[Bn * Cn * Ln];   // [b][c][k]
__device__ __nv_bfloat16 g_V_l[Bn * Cn * Ln];

// ---------------- helpers ----------------
__device__ __forceinline__ uint32_t smem_u32(const void* p) {
    uint32_t a;
    asm("{ .reg .u64 t; cvta.to.shared.u64 t, %1; cvt.u32.u64 %0, t; }" : "=r"(a) : "l"(p));
    return a;
}

__device__ __forceinline__ void ldsm4(uint32_t* r, uint32_t addr) {
    asm volatile("ldmatrix.sync.aligned.m8n8.x4.shared.b16 {%0,%1,%2,%3}, [%4];"
        : "=r"(r[0]), "=r"(r[1]), "=r"(r[2]), "=r"(r[3]) : "r"(addr));
}
__device__ __forceinline__ void ldsm4t(uint32_t* r, uint32_t addr) {
    asm volatile("ldmatrix.sync.aligned.m8n8.x4.trans.shared.b16 {%0,%1,%2,%3}, [%4];"
        : "=r"(r[0]), "=r"(r[1]), "=r"(r[2]), "=r"(r[3]) : "r"(addr));
}
__device__ __forceinline__ void mma_bf16(float* d, const uint32_t* a, const uint32_t* b) {
    asm volatile(
        "mma.sync.aligned.m16n8k16.row.col.f32.bf16.bf16.f32 "
        "{%0,%1,%2,%3}, {%4,%5,%6,%7}, {%8,%9}, {%0,%1,%2,%3};"
        : "+f"(d[0]), "+f"(d[1]), "+f"(d[2]), "+f"(d[3])
        : "r"(a[0]), "r"(a[1]), "r"(a[2]), "r"(a[3]), "r"(b[0]), "r"(b[1]));
}

__device__ __forceinline__ void split_bf16(float x, __nv_bfloat16& h, __nv_bfloat16& l) {
    h = __float2bfloat16_rn(x);
    l = __float2bfloat16_rn(x - __bfloat162float(h));
}

// XOR swizzle, pitch 256B (16 groups of 16B) or 128B (8 groups)
__device__ __forceinline__ uint32_t swz256(int row, int g) {
    return (uint32_t)(row * 256 + ((g ^ (row & 7)) * 16));
}
__device__ __forceinline__ uint32_t swz128(int row, int g) {
    return (uint32_t)(row * 128 + ((g ^ (row & 7)) * 16));
}

// ---------------------------------------------------------------------------
// prep_t: transpose+convert Q,K  [b][c][l] f32 -> [b][l][c] bf16 hi/lo
// ---------------------------------------------------------------------------
__global__ __launch_bounds__(256) void prep_t(const float* __restrict__ Q,
                                              const float* __restrict__ K)
{
    __shared__ float tile[32][33];
    int z = blockIdx.z;
    int b = z & 15;
    const float* src = (z < 16) ? Q : K;
    __nv_bfloat16* dh = (z < 16) ? g_Qt_h : g_Kt_h;
    __nv_bfloat16* dl = (z < 16) ? g_Qt_l : g_Kt_l;
    src += (size_t)b * Cn * Ln;

    int l0 = blockIdx.x * 32, c0 = blockIdx.y * 32;
    int tx = threadIdx.x & 31, ty = threadIdx.x >> 5;
#pragma unroll
    for (int i = 0; i < 4; i++) {
        int c = ty + i * 8;
        tile[tx][c] = src[(size_t)(c0 + c) * Ln + l0 + tx];
    }
    __syncthreads();
#pragma unroll
    for (int i = 0; i < 4; i++) {
        int lr = ty + i * 8;
        float v = tile[lr][tx];
        __nv_bfloat16 h, l;
        split_bf16(v, h, l);
        size_t o = ((size_t)b * Ln + l0 + lr) * Cn + c0 + tx;
        dh[o] = h;
        dl[o] = l;
    }
}

// prep_v: convert V f32 -> bf16 hi/lo (layout unchanged)
__global__ __launch_bounds__(256) void prep_v(const float* __restrict__ V)
{
    size_t i = (size_t)blockIdx.x * 256 + threadIdx.x;  // float4 index
    float4 v = ((const float4*)V)[i];
    __nv_bfloat16 h[4], l[4];
    split_bf16(v.x, h[0], l[0]); split_bf16(v.y, h[1], l[1]);
    split_bf16(v.z, h[2], l[2]); split_bf16(v.w, h[3], l[3]);
    __nv_bfloat162* ph = (__nv_bfloat162*)(g_V_h + i * 4);
    __nv_bfloat162* pl = (__nv_bfloat162*)(g_V_l + i * 4);
    ph[0] = __halves2bfloat162(h[0], h[1]); ph[1] = __halves2bfloat162(h[2], h[3]);
    pl[0] = __halves2bfloat162(l[0], l[1]); pl[1] = __halves2bfloat162(l[2], l[3]);
}

// ---------------------------------------------------------------------------
// K1: P[b,k,q] = exp(score*rsqrtC + logmask) via mma.sync bf16 3-term split.
// Tile 128(k) x 64(q), Kdim = c = 128. 8 warps = 4(m) x 2(n), warp 32x32.
// smem: lm[128f] | psum[64][4]f | Ah 32K | Al 32K | Bh 16K | Bl 16K
// ---------------------------------------------------------------------------
#define S1_TOTAL (2048 + 98304)

__global__ __launch_bounds__(256) void k1_mma(const float* __restrict__ mask,
                                              float* __restrict__ attn)
{
    extern __shared__ char sm[];
    float* lmS  = (float*)sm;              // 128 floats
    float* psum = (float*)(sm + 512);      // [64][4]
    char* Ah = sm + 2048;
    char* Al = Ah + 32768;
    char* Bh = Al + 32768;
    char* Bl = Bh + 16384;

    int t = threadIdx.x;
    int b = blockIdx.z, kb = blockIdx.y, qb = blockIdx.x;
    int k0 = kb * 128, q0 = qb * 64;

    // stage A = Kt rows [k0, k0+128), 128 c each (256B contiguous rows)
    const uint4* kh = (const uint4*)(g_Kt_h + ((size_t)b * Ln + k0) * Cn);
    const uint4* kl = (const uint4*)(g_Kt_l + ((size_t)b * Ln + k0) * Cn);
#pragma unroll
    for (int i = 0; i < 8; i++) {
        int idx = t + i * 256, row = idx >> 4, g = idx & 15;
        uint32_t off = swz256(row, g);
        *(uint4*)(Ah + off) = kh[idx];
        *(uint4*)(Al + off) = kl[idx];
    }
    // stage B = Qt rows [q0, q0+64)
    const uint4* qh = (const uint4*)(g_Qt_h + ((size_t)b * Ln + q0) * Cn);
    const uint4* ql = (const uint4*)(g_Qt_l + ((size_t)b * Ln + q0) * Cn);
#pragma unroll
    for (int i = 0; i < 4; i++) {
        int idx = t + i * 256, row = idx >> 4, g = idx & 15;
        uint32_t off = swz256(row, g);
        *(uint4*)(Bh + off) = qh[idx];
        *(uint4*)(Bl + off) = ql[idx];
    }
    if (t < 128) lmS[t] = __logf(__ldg(mask + b * Ln + k0 + t) + 1e-6f);
    __syncthreads();

    int w = t >> 5, l = t & 31;
    int wm = w & 3, wn = w >> 2;
    int mb0 = wm * 32, nb0 = wn * 32;

    float acc[2][4][4];
#pragma unroll
    for (int mt = 0; mt < 2; mt++)
#pragma unroll
        for (int nt = 0; nt < 4; nt++)
#pragma unroll
            for (int e = 0; e < 4; e++) acc[mt][nt][e] = 0.f;

    uint32_t sAh = smem_u32(Ah), sAl = smem_u32(Al);
    uint32_t sBh = smem_u32(Bh), sBl = smem_u32(Bl);

    int lrow8 = (l & 7) + ((l >> 3) & 1) * 8;   // row within 16 for ldsm x4
    int lgsel = (l >> 4) & 1;                   // k-half select (lanes 16-31)
    int bgsel = (l >> 3) & 1;                   // B: g select
    int brow8 = ((l >> 4) & 1) * 8 + (l & 7);   // B: row within 16

#pragma unroll
    for (int seg = 0; seg < 3; seg++) {
        uint32_t aBase = (seg == 2) ? sAl : sAh;
        uint32_t bBase = (seg == 1) ? sBl : sBh;
#pragma unroll
        for (int ks = 0; ks < 8; ks++) {
            uint32_t afr[2][4];
#pragma unroll
            for (int mt = 0; mt < 2; mt++) {
                int row = mb0 + mt * 16 + lrow8;
                ldsm4(afr[mt], aBase + swz256(row, ks * 2 + lgsel));
            }
            uint32_t bf[2][4];
#pragma unroll
            for (int np = 0; np < 2; np++) {
                int row = nb0 + np * 16 + brow8;
                ldsm4(bf[np], bBase + swz256(row, ks * 2 + bgsel));
            }
#pragma unroll
            for (int mt = 0; mt < 2; mt++)
#pragma unroll
                for (int nt = 0; nt < 4; nt++)
                    mma_bf16(acc[mt][nt], afr[mt], &bf[nt >> 1][(nt & 1) * 2]);
        }
    }

    // epilogue: exp, store P, per-q partial sums
    int lq = (l & 3) * 2;
    int lr = l >> 2;
    float qs[4][2];
#pragma unroll
    for (int nt = 0; nt < 4; nt++) { qs[nt][0] = 0.f; qs[nt][1] = 0.f; }

#pragma unroll
    for (int mt = 0; mt < 2; mt++) {
        int krow = mb0 + mt * 16 + lr;
        float lm0 = lmS[krow], lm1 = lmS[krow + 8];
#pragma unroll
        for (int nt = 0; nt < 4; nt++) {
            float e0 = __expf(fmaf(acc[mt][nt][0], RSQRTC, lm0));
            float e1 = __expf(fmaf(acc[mt][nt][1], RSQRTC, lm0));
            float e2 = __expf(fmaf(acc[mt][nt][2], RSQRTC, lm1));
            float e3 = __expf(fmaf(acc[mt][nt][3], RSQRTC, lm1));
            size_t base = ((size_t)b << 22) + (size_t)(k0 + krow) * Ln
                        + q0 + nb0 + nt * 8 + lq;
            *(float2*)(attn + base)          = make_float2(e0, e1);
            *(float2*)(attn + base + 8 * Ln) = make_float2(e2, e3);
            qs[nt][0] += e0 + e2;
            qs[nt][1] += e1 + e3;
        }
    }
#pragma unroll
    for (int nt = 0; nt < 4; nt++)
#pragma unroll
        for (int s = 4; s < 32; s <<= 1) {
            qs[nt][0] += __shfl_xor_sync(0xFFFFFFFFu, qs[nt][0], s);
            qs[nt][1] += __shfl_xor_sync(0xFFFFFFFFu, qs[nt][1], s);
        }
    if (l < 4) {
#pragma unroll
        for (int nt = 0; nt < 4; nt++) {
            int nl = nb0 + nt * 8 + l * 2;
            psum[(nl + 0) * 4 + wm] = qs[nt][0];
            psum[(nl + 1) * 4 + wm] = qs[nt][1];
        }
    }
    __syncthreads();
    if (t < 64) {
        float S = psum[t * 4 + 0] + psum[t * 4 + 1] + psum[t * 4 + 2] + psum[t * 4 + 3];
        g_ps[((size_t)(b * Ln + q0 + t)) * NKB + kb] = S;
    }
}

// ---------------------------------------------------------------------------
// K2: combine split-K partial sums -> 1/S per (b,q)
// ---------------------------------------------------------------------------
__global__ __launch_bounds__(256) void k_sinv()
{
    int i = blockIdx.x * 256 + threadIdx.x;
    float S = 0.f;
#pragma unroll
    for (int c = 0; c < NKB; c++) S += g_ps[(size_t)i * NKB + c];
    g_Sinv[i] = 1.f / S;
}

// ---------------------------------------------------------------------------
// K3: w = P*Sinv*mask (written back as final attention) ; out = V @ w.
// Tile 128(c) x 64(q), 16 chunks of k=128. A=V [c][k] via ldsm; B=w [k][q]
// via ldsm.trans. 8 warps = 4(m) x 2(n).
// smem: Vh 32K | Vl 32K | Wh 16K | Wl 16K = 96K
// ---------------------------------------------------------------------------
#define S3_TOTAL 98304

__global__ __launch_bounds__(256) void k3_mma(const float* __restrict__ mask,
                                              float* __restrict__ attn,
                                              float* __restrict__ out)
{
    extern __shared__ char sm[];
    char* Vh = sm;
    char* Vl = sm + 32768;
    char* Wh = sm + 65536;
    char* Wl = sm + 81920;

    int t = threadIdx.x;
    int b = blockIdx.y, q0 = blockIdx.x * 64;
    int w = t >> 5, l = t & 31;
    int wm = w & 3, wn = w >> 2;
    int mb0 = wm * 32, nb0 = wn * 32;

    float acc[2][4][4];
#pragma unroll
    for (int mt = 0; mt < 2; mt++)
#pragma unroll
        for (int nt = 0; nt < 4; nt++)
#pragma unroll
            for (int e = 0; e < 4; e++) acc[mt][nt][e] = 0.f;

    uint32_t sVh = smem_u32(Vh), sVl = smem_u32(Vl);
    uint32_t sWh = smem_u32(Wh), sWl = smem_u32(Wl);

    const uint4* vh = (const uint4*)(g_V_h + (size_t)b * Cn * Ln);
    const uint4* vl = (const uint4*)(g_V_l + (size_t)b * Cn * Ln);

    int q4  = t & 15;                      // float4 slot within 64 q
    int kr0 = t >> 4;                      // base k-row for staging
    float4 si = *(const float4*)(g_Sinv + (size_t)b * Ln + q0 + q4 * 4);

    int lrow8 = (l & 7) + ((l >> 3) & 1) * 8;
    int lgsel = (l >> 4) & 1;

    for (int ch = 0; ch < 16; ch++) {
        int k0c = ch * 128;
        // stage V chunk: rows c=128, 16 groups of 16B (=128 k bf16)
#pragma unroll
        for (int i = 0; i < 8; i++) {
            int idx = t + i * 256, row = idx >> 4, g = idx & 15;
            uint32_t off = swz256(row, g);
            *(uint4*)(Vh + off) = vh[(size_t)row * (Ln / 8) + k0c / 8 + g];
            *(uint4*)(Vl + off) = vl[(size_t)row * (Ln / 8) + k0c / 8 + g];
        }
        // stage w: normalize P, write back final attention, bf16 hi/lo to smem
#pragma unroll
        for (int i = 0; i < 8; i++) {
            int krow = kr0 + i * 16;
            size_t aidx = ((size_t)b << 22) + (size_t)(k0c + krow) * Ln + q0 + q4 * 4;
            float4 p = *(float4*)(attn + aidx);
            float mk = __ldg(mask + b * Ln + k0c + krow);
            p.x *= si.x * mk; p.y *= si.y * mk; p.z *= si.z * mk; p.w *= si.w * mk;
            *(float4*)(attn + aidx) = p;     // final attention output
            __nv_bfloat16 h0, l0, h1, l1, h2, l2, h3, l3;
            split_bf16(p.x, h0, l0); split_bf16(p.y, h1, l1);
            split_bf16(p.z, h2, l2); split_bf16(p.w, h3, l3);
            uint32_t off = swz128(krow, q4 >> 1) + (q4 & 1) * 8;
            ((__nv_bfloat162*)(Wh + off))[0] = __halves2bfloat162(h0, h1);
            ((__nv_bfloat162*)(Wh + off))[1] = __halves2bfloat162(h2, h3);
            ((__nv_bfloat162*)(Wl + off))[0] = __halves2bfloat162(l0, l1);
            ((__nv_bfloat162*)(Wl + off))[1] = __halves2bfloat162(l2, l3);
        }
        __syncthreads();

#pragma unroll
        for (int seg = 0; seg < 3; seg++) {
            uint32_t aBase = (seg == 2) ? sVl : sVh;
            uint32_t bBase = (seg == 1) ? sWl : sWh;
#pragma unroll
            for (int ks = 0; ks < 8; ks++) {
                uint32_t afr[2][4];
#pragma unroll
                for (int mt = 0; mt < 2; mt++) {
                    int row = mb0 + mt * 16 + lrow8;
                    ldsm4(afr[mt], aBase + swz256(row, ks * 2 + lgsel));
                }
                uint32_t bf[2][4];
#pragma unroll
                for (int np = 0; np < 2; np++) {
                    int row = ks * 16 + lrow8;
                    int qg  = wn * 4 + np * 2 + lgsel;
                    ldsm4t(bf[np], bBase + swz128(row, qg));
                }
#pragma unroll
                for (int mt = 0; mt < 2; mt++)
#pragma unroll
                    for (int nt = 0; nt < 4; nt++)
                        mma_bf16(acc[mt][nt], afr[mt], &bf[nt >> 1][(nt & 1) * 2]);
            }
        }
        __syncthreads();
    }

    // epilogue: D[c][q] -> out
    int lq = (l & 3) * 2;
    int lr = l >> 2;
#pragma unroll
    for (int mt = 0; mt < 2; mt++) {
        int c0 = mb0 + mt * 16 + lr;
#pragma unroll
        for (int nt = 0; nt < 4; nt++) {
            int q = q0 + nb0 + nt * 8 + lq;
            float* dst = out + ((size_t)b * Cn + c0) * Ln + q;
            *(float2*)dst            = make_float2(acc[mt][nt][0], acc[mt][nt][1]);
            *(float2*)(dst + 8 * Ln) = make_float2(acc[mt][nt][2], acc[mt][nt][3]);
        }
    }
}

// ---------------------------------------------------------------------------
extern "C" void kernel_launch(void* const* d_in, const int* in_sizes, int n_in,
                              void* d_out, int out_size)
{
    const float* Q    = (const float*)d_in[0];
    const float* K    = (const float*)d_in[1];
    const float* V    = (const float*)d_in[2];
    const float* mask = (const float*)d_in[3];

    float* out  = (float*)d_out;                      // [B, C, L]
    float* attn = out + (size_t)Bn * Cn * Ln;         // [B, Lk, Lq] (transposed)

    cudaFuncSetAttribute(k1_mma, cudaFuncAttributeMaxDynamicSharedMemorySize, S1_TOTAL);
    cudaFuncSetAttribute(k3_mma, cudaFuncAttributeMaxDynamicSharedMemorySize, S3_TOTAL);

    dim3 gt(Ln / 32, Cn / 32, 2 * Bn);
    prep_t<<<gt, 256>>>(Q, K);
    prep_v<<<(Bn * Cn * Ln / 4) / 256, 256>>>(V);

    dim3 g1(Ln / 64, Ln / 128, Bn);
    k1_mma<<<g1, 256, S1_TOTAL>>>(mask, attn);

    k_sinv<<<(Bn * Ln) / 256, 256>>>();

    dim3 g3(Ln / 64, Bn);
    k3_mma<<<g3, 256, S3_TOTAL>>>(mask, attn, out);
}